// round 1
// baseline (speedup 1.0000x reference)
#include <cuda_runtime.h>
#include <cstdint>
#include <cstddef>

// Problem constants
#define LSEQ 128
#define BSZ  32
#define EDIM 512
#define DDIM 1024
#define VDIM 32000
#define MIDN 4
#define MROWS (LSEQ*BSZ)   // 4096

// ---------------------------------------------------------------------------
// Scratch (device globals; no allocation allowed)
// ---------------------------------------------------------------------------
__device__ float gX0[MROWS * EDIM];          // embedding output / layer inputs (E wide)
__device__ float gH [MROWS * DDIM];          // activations between D-wide layers
__device__ float gHF[MROWS * EDIM];          // final layer output
__device__ float gU [MROWS * 4 * DDIM];      // U scratch (max 4096 x 4096)

// ---------------------------------------------------------------------------
// Packed f32x2 helpers (Blackwell FFMA2 path)
// ---------------------------------------------------------------------------
__device__ __forceinline__ unsigned long long pk2(float lo, float hi) {
    unsigned long long r;
    asm("mov.b64 %0, {%1, %2};" : "=l"(r) : "f"(lo), "f"(hi));
    return r;
}
__device__ __forceinline__ void upk2(unsigned long long v, float& lo, float& hi) {
    asm("mov.b64 {%0, %1}, %2;" : "=f"(lo), "=f"(hi) : "l"(v));
}
__device__ __forceinline__ void ffma2(unsigned long long& c,
                                      unsigned long long a, unsigned long long b) {
    asm("fma.rn.f32x2 %0, %1, %2, %0;" : "+l"(c) : "l"(a), "l"(b));
}

// ---------------------------------------------------------------------------
// Embedding gather (with int32/int64 token dtype detection)
// ---------------------------------------------------------------------------
__global__ void embed_gather(const int* __restrict__ x32,
                             const float* __restrict__ emb,
                             float* __restrict__ out) {
    int row = blockIdx.x;  // 0..4095 (= l*B + b)
    // If tokens are int64 little-endian, every odd 32-bit word is 0.
    bool is64 = (x32[1] == 0) && (x32[3] == 0) && (x32[5] == 0) && (x32[7] == 0);
    long long idx = is64 ? ((const long long*)x32)[row] : (long long)x32[row];
    const float4* src = (const float4*)(emb + (size_t)idx * EDIM);
    float4* dst = (float4*)(out + (size_t)row * EDIM);
    dst[threadIdx.x] = src[threadIdx.x];   // 128 threads x float4 = 512 floats
}

// ---------------------------------------------------------------------------
// SGEMM: C[M,N] = A[M,K] @ B (+ bias). BT=false: B is [K,N] row-major.
// BT=true: B is [N,K] row-major (i.e. C = A @ B^T) — used for logits vs emb.
// 128x128 block tile, BK=16, 256 threads, 8x8 register tile, f32x2 FMA core.
// All dims are multiples of the tile sizes for this problem (32000 = 250*128).
// ---------------------------------------------------------------------------
#define BM 128
#define BN 128
#define BK 16

template <bool BT>
__global__ void __launch_bounds__(256)
sgemm_k(const float* __restrict__ A, const float* __restrict__ B,
        float* __restrict__ C, const float* __restrict__ bias,
        int M, int N, int K) {
    __shared__ float As[BK][BM];
    __shared__ float Bs[BK][BN];

    const int tid = threadIdx.x;
    const int tx = tid & 15;        // 0..15 -> n sub-tile
    const int ty = tid >> 4;        // 0..15 -> m sub-tile
    const int m0 = blockIdx.y * BM;
    const int n0 = blockIdx.x * BN;

    unsigned long long acc[8][4];
#pragma unroll
    for (int i = 0; i < 8; i++)
#pragma unroll
        for (int j = 0; j < 4; j++) acc[i][j] = 0ull;

    for (int kt = 0; kt < K; kt += BK) {
        // ---- load A tile (transpose into As[k][m]) ----
#pragma unroll
        for (int it = 0; it < 2; it++) {
            int p  = tid + it * 256;         // 0..511
            int r  = p >> 2;                 // 0..127 row (m)
            int c4 = (p & 3) * 4;            // 0,4,8,12 col (k)
            float4 v = *(const float4*)(A + (size_t)(m0 + r) * K + kt + c4);
            As[c4 + 0][r] = v.x; As[c4 + 1][r] = v.y;
            As[c4 + 2][r] = v.z; As[c4 + 3][r] = v.w;
        }
        // ---- load B tile ----
        if (!BT) {
#pragma unroll
            for (int it = 0; it < 2; it++) {
                int p  = tid + it * 256;
                int r  = p >> 5;             // 0..15 row (k)
                int c4 = (p & 31) * 4;       // col (n)
                float4 v = *(const float4*)(B + (size_t)(kt + r) * N + n0 + c4);
                *(float4*)&Bs[r][c4] = v;
            }
        } else {
#pragma unroll
            for (int it = 0; it < 2; it++) {
                int p  = tid + it * 256;
                int r  = p >> 2;             // 0..127 row (n)
                int c4 = (p & 3) * 4;        // col (k)
                float4 v = *(const float4*)(B + (size_t)(n0 + r) * K + kt + c4);
                Bs[c4 + 0][r] = v.x; Bs[c4 + 1][r] = v.y;
                Bs[c4 + 2][r] = v.z; Bs[c4 + 3][r] = v.w;
            }
        }
        __syncthreads();

        // ---- compute: 8x8 per thread, packed f32x2 FMAs ----
#pragma unroll
        for (int kk = 0; kk < BK; kk++) {
            float a[8], b[8];
            *(float4*)&a[0] = *(const float4*)&As[kk][ty * 8];
            *(float4*)&a[4] = *(const float4*)&As[kk][ty * 8 + 4];
            *(float4*)&b[0] = *(const float4*)&Bs[kk][tx * 8];
            *(float4*)&b[4] = *(const float4*)&Bs[kk][tx * 8 + 4];
            unsigned long long pb[4];
#pragma unroll
            for (int j = 0; j < 4; j++) pb[j] = pk2(b[2 * j], b[2 * j + 1]);
#pragma unroll
            for (int i = 0; i < 8; i++) {
                unsigned long long pa = pk2(a[i], a[i]);
#pragma unroll
                for (int j = 0; j < 4; j++) ffma2(acc[i][j], pa, pb[j]);
            }
        }
        __syncthreads();
    }

    // ---- epilogue ----
#pragma unroll
    for (int i = 0; i < 8; i++) {
        int m = m0 + ty * 8 + i;
        float out[8];
#pragma unroll
        for (int j = 0; j < 4; j++) upk2(acc[i][j], out[2 * j], out[2 * j + 1]);
        if (bias) {
#pragma unroll
            for (int j = 0; j < 8; j++) out[j] += bias[n0 + tx * 8 + j];
        }
        float* cp = C + (size_t)m * N + n0 + tx * 8;
        *(float4*)cp       = *(float4*)&out[0];
        *(float4*)(cp + 4) = *(float4*)&out[4];
    }
}

// ---------------------------------------------------------------------------
// SRU recurrence: per-(b,d) channel scan over L.
// U row layout: [x_tilde | f_pre | r_pre | (hw if k==4)], stride = ustride.
// If hwIn != nullptr (k==3 layers), hw comes from the layer input (residual).
// ---------------------------------------------------------------------------
__device__ __forceinline__ float sigm(float x) { return 1.0f / (1.0f + expf(-x)); }

__global__ void sru_scan(const float* __restrict__ U, int ustride,
                         const float* __restrict__ hwIn,
                         const float* __restrict__ bias,
                         const float* __restrict__ c0,
                         float* __restrict__ H, int n_out) {
    int t = blockIdx.x * blockDim.x + threadIdx.x;
    int total = BSZ * n_out;
    if (t >= total) return;
    int b = t / n_out;
    int d = t - b * n_out;

    float c  = c0[t];
    float bf = bias[d];
    float br = bias[n_out + d];

    for (int l = 0; l < LSEQ; l++) {
        size_t rowi = (size_t)(l * BSZ + b);
        const float* row = U + rowi * ustride;
        float xt = row[d];
        float f  = sigm(row[n_out + d] + bf);
        float r  = sigm(row[2 * n_out + d] + br);
        float hw = hwIn ? hwIn[rowi * n_out + d] : row[3 * n_out + d];
        c = f * c + (1.0f - f) * xt;
        float g = tanhf(c);
        H[rowi * n_out + d] = r * g + (1.0f - r) * hw;
    }
}

// ---------------------------------------------------------------------------
// Launch
// ---------------------------------------------------------------------------
extern "C" void kernel_launch(void* const* d_in, const int* in_sizes, int n_in,
                              void* d_out, int out_size) {
    const int*   x        = (const int*)  d_in[0];
    const float* c1       = (const float*)d_in[1];   // (B, D)
    const float* c2       = (const float*)d_in[2];   // (MID, B, D)
    const float* c3       = (const float*)d_in[3];   // (B, E)
    const float* emb      = (const float*)d_in[4];   // (V, E)
    const float* out_bias = (const float*)d_in[5];   // (V,)
    const float* W1       = (const float*)d_in[6];   // (E, 4D)
    const float* b1       = (const float*)d_in[7];   // (2D,)
    const float* W2       = (const float*)d_in[8];   // (MID, D, 3D)
    const float* b2       = (const float*)d_in[9];   // (MID, 2D)
    const float* W3       = (const float*)d_in[10];  // (D, 4E)
    const float* b3       = (const float*)d_in[11];  // (2E,)
    float* out = (float*)d_out;

    float *X0, *H, *HF, *U;
    cudaGetSymbolAddress((void**)&X0, gX0);
    cudaGetSymbolAddress((void**)&H,  gH);
    cudaGetSymbolAddress((void**)&HF, gHF);
    cudaGetSymbolAddress((void**)&U,  gU);

    // 1) Embedding gather -> X0 (4096 x 512)
    embed_gather<<<MROWS, 128>>>(x, emb, X0);

    // 2) Layer 1 (k=4): U = X0 @ W1  (4096 x 4096), scan -> H (4096 x 1024)
    sgemm_k<false><<<dim3(4 * DDIM / BN, MROWS / BM), 256>>>(
        X0, W1, U, nullptr, MROWS, 4 * DDIM, EDIM);
    sru_scan<<<(BSZ * DDIM + 255) / 256, 256>>>(U, 4 * DDIM, nullptr, b1, c1, H, DDIM);

    // 3) Middle layers (k=3): U = H @ W2[i]  (4096 x 3072), scan in-place on H
    for (int i = 0; i < MIDN; i++) {
        const float* Wi = W2 + (size_t)i * DDIM * 3 * DDIM;
        const float* bi = b2 + (size_t)i * 2 * DDIM;
        const float* ci = c2 + (size_t)i * BSZ * DDIM;
        sgemm_k<false><<<dim3(3 * DDIM / BN, MROWS / BM), 256>>>(
            H, Wi, U, nullptr, MROWS, 3 * DDIM, DDIM);
        sru_scan<<<(BSZ * DDIM + 255) / 256, 256>>>(U, 3 * DDIM, H, bi, ci, H, DDIM);
    }

    // 4) Final layer (k=4): U = H @ W3 (4096 x 2048), scan -> HF (4096 x 512)
    sgemm_k<false><<<dim3(4 * EDIM / BN, MROWS / BM), 256>>>(
        H, W3, U, nullptr, MROWS, 4 * EDIM, DDIM);
    sru_scan<<<(BSZ * EDIM + 255) / 256, 256>>>(U, 4 * EDIM, nullptr, b3, c3, HF, EDIM);

    // 5) Logits: out = HF @ emb^T + out_bias  (4096 x 32000)
    sgemm_k<true><<<dim3(VDIM / BN, MROWS / BM), 256>>>(
        HF, emb, out, out_bias, MROWS, VDIM, EDIM);
}

// round 4
// speedup vs baseline: 2.6438x; 2.6438x over previous
#include <cuda_runtime.h>
#include <cstdint>
#include <cstddef>

// Problem constants
#define LSEQ 128
#define BSZ  32
#define EDIM 512
#define DDIM 1024
#define VDIM 32000
#define MIDN 4
#define MROWS (LSEQ*BSZ)   // 4096

// ---------------------------------------------------------------------------
// Scratch (device globals; no allocation allowed)
// ---------------------------------------------------------------------------
__device__ float gH [MROWS * DDIM];     // fp32 activations (residual/hw path)
__device__ float gU [MROWS * 4 * DDIM]; // U scratch (4096 x 4096 max)
__device__ float gAr[MROWS * DDIM];     // tf32-rounded A (GEMM input)
__device__ float gBr[VDIM * EDIM];      // tf32-rounded B ([N,K]; max 32000x512)

__device__ __forceinline__ uint32_t smem_u32(const void* p) {
    uint32_t a;
    asm("{ .reg .u64 t; cvta.to.shared.u64 t, %1; cvt.u32.u64 %0, t; }" : "=r"(a) : "l"(p));
    return a;
}
__device__ __forceinline__ float tf32r(float v) {
    uint32_t o;
    asm("cvt.rna.tf32.f32 %0, %1;" : "=r"(o) : "f"(v));
    return __uint_as_float(o);
}

// SW128 swizzle on byte offsets within a tile of 128B rows
#define SWZ(off) ((off) ^ (((off) >> 3) & 0x70))

// ---------------------------------------------------------------------------
// Embedding gather -> tf32-rounded A (int32/int64 token dtype detection)
// ---------------------------------------------------------------------------
__global__ void embed_gather(const int* __restrict__ x32,
                             const float* __restrict__ emb,
                             float* __restrict__ outR) {
    int row = blockIdx.x;
    bool is64 = (x32[1] == 0) && (x32[3] == 0) && (x32[5] == 0) && (x32[7] == 0);
    long long idx = is64 ? ((const long long*)x32)[row] : (long long)x32[row];
    float4 v = ((const float4*)(emb + (size_t)idx * EDIM))[threadIdx.x];
    v.x = tf32r(v.x); v.y = tf32r(v.y); v.z = tf32r(v.z); v.w = tf32r(v.w);
    ((float4*)(outR + (size_t)row * EDIM))[threadIdx.x] = v;
}

// ---------------------------------------------------------------------------
// tf32 rounding kernels (weights / emb)
// ---------------------------------------------------------------------------
__global__ void conv_round(const float* __restrict__ in, float* __restrict__ out, int n4) {
    int i = blockIdx.x * blockDim.x + threadIdx.x;
    if (i >= n4) return;
    float4 v = ((const float4*)in)[i];
    v.x = tf32r(v.x); v.y = tf32r(v.y); v.z = tf32r(v.z); v.w = tf32r(v.w);
    ((float4*)out)[i] = v;
}

// transpose + round: in [R, C] -> out [C, R]. R,C multiples of 32.
__global__ void conv_round_T(const float* __restrict__ in, int R, int C,
                             float* __restrict__ out) {
    __shared__ float t[32][33];
    int c0 = blockIdx.x * 32, r0 = blockIdx.y * 32;
    int tx = threadIdx.x;
    for (int i = threadIdx.y; i < 32; i += 8)
        t[i][tx] = in[(size_t)(r0 + i) * C + c0 + tx];
    __syncthreads();
    for (int i = threadIdx.y; i < 32; i += 8)
        out[(size_t)(c0 + i) * R + r0 + tx] = tf32r(t[tx][i]);
}

// ---------------------------------------------------------------------------
// tf32 mma.sync GEMM: C[M,N] = A[M,K] @ B[N,K]^T (+bias)
// BM=BN=128, BK=32 f32 (128B rows, SW128 swizzle), 4-stage cp.async pipeline.
// 256 threads = 8 warps (2 m x 4 n), warp tile 64x32, m16n8k8 tf32 HMMA.
// ---------------------------------------------------------------------------
#define STAGES 4
#define BKC 32
#define STG_BYTES 32768                 // A tile 16KB + B tile 16KB
#define GEMM_SMEM (STAGES * STG_BYTES)  // 131072

__device__ __forceinline__ void cp16(uint32_t sa, const float* ga) {
    asm volatile("cp.async.cg.shared.global [%0], [%1], 16;" :: "r"(sa), "l"(ga) : "memory");
}

__global__ void __launch_bounds__(256, 1)
gemm_tf32(const float* __restrict__ A, const float* __restrict__ B,
          float* __restrict__ C, const float* __restrict__ bias,
          int M, int N, int K) {
    extern __shared__ char smem[];
    const uint32_t sb = smem_u32(smem);
    const int tid = threadIdx.x;
    const int wid = tid >> 5, lane = tid & 31;
    const int wm = wid & 1, wn = wid >> 1;
    const int m0 = blockIdx.y * 128;
    const int n0 = blockIdx.x * 128;

    const float* Ag = A + (size_t)m0 * K;
    const float* Bg = B + (size_t)n0 * K;

    const int nch = K / BKC;

    auto load_stage = [&](int ch, int slot) {
        const uint32_t sA = sb + slot * STG_BYTES;
        const uint32_t sB = sA + 16384;
        const int kt = ch * BKC;
#pragma unroll
        for (int it = 0; it < 4; it++) {
            int u = tid + it * 256;          // 0..1023
            int row = u >> 3, c = u & 7;
            uint32_t so = SWZ(row * 128 + c * 16);
            cp16(sA + so, Ag + (size_t)row * K + kt + c * 4);
            cp16(sB + so, Bg + (size_t)row * K + kt + c * 4);
        }
    };

#pragma unroll
    for (int s = 0; s < STAGES - 1; s++) {
        if (s < nch) load_stage(s, s);
        asm volatile("cp.async.commit_group;" ::: "memory");
    }

    float acc[64];
#pragma unroll
    for (int i = 0; i < 64; i++) acc[i] = 0.0f;

    const int lr = lane & 7, g = lane >> 3;
    const int arow_b = wm * 64 + ((g & 1) << 3) + lr;   // + t*16
    const int brow_b = wn * 32 + ((g & 1) << 3) + lr;   // + u*16
    const int chk_b = g >> 1;                           // + ks*2

    for (int ch = 0; ch < nch; ch++) {
        asm volatile("cp.async.wait_group %0;" :: "n"(STAGES - 2) : "memory");
        __syncthreads();

        {
            int nx = ch + STAGES - 1;
            if (nx < nch) load_stage(nx, nx % STAGES);
            asm volatile("cp.async.commit_group;" ::: "memory");
        }

        const uint32_t sA = sb + (ch % STAGES) * STG_BYTES;
        const uint32_t sB = sA + 16384;

#pragma unroll
        for (int ks = 0; ks < 4; ks++) {
            const int chunk = ks * 2 + chk_b;
            uint32_t a[4][4], bf[2][4];
#pragma unroll
            for (int t = 0; t < 4; t++) {
                uint32_t ad = sA + SWZ((arow_b + t * 16) * 128 + chunk * 16);
                asm volatile("ldmatrix.sync.aligned.m8n8.x4.shared.b16 {%0,%1,%2,%3}, [%4];"
                             : "=r"(a[t][0]), "=r"(a[t][1]), "=r"(a[t][2]), "=r"(a[t][3])
                             : "r"(ad));
            }
#pragma unroll
            for (int u = 0; u < 2; u++) {
                uint32_t bd = sB + SWZ((brow_b + u * 16) * 128 + chunk * 16);
                asm volatile("ldmatrix.sync.aligned.m8n8.x4.shared.b16 {%0,%1,%2,%3}, [%4];"
                             : "=r"(bf[u][0]), "=r"(bf[u][1]), "=r"(bf[u][2]), "=r"(bf[u][3])
                             : "r"(bd));
            }
#pragma unroll
            for (int mt = 0; mt < 4; mt++) {
#pragma unroll
                for (int nt = 0; nt < 4; nt++) {
                    uint32_t b0 = bf[nt >> 1][nt & 1];
                    uint32_t b1 = bf[nt >> 1][(nt & 1) + 2];
                    float* c = &acc[mt * 16 + nt * 4];
                    asm volatile(
                        "mma.sync.aligned.m16n8k8.row.col.f32.tf32.tf32.f32 "
                        "{%0,%1,%2,%3}, {%4,%5,%6,%7}, {%8,%9}, {%0,%1,%2,%3};"
                        : "+f"(c[0]), "+f"(c[1]), "+f"(c[2]), "+f"(c[3])
                        : "r"(a[mt][0]), "r"(a[mt][1]), "r"(a[mt][2]), "r"(a[mt][3]),
                          "r"(b0), "r"(b1));
                }
            }
        }
    }

    // ---- epilogue ----
#pragma unroll
    for (int mt = 0; mt < 4; mt++) {
        int r = m0 + wm * 64 + mt * 16 + (lane >> 2);
#pragma unroll
        for (int nt = 0; nt < 4; nt++) {
            int cc = n0 + wn * 32 + nt * 8 + (lane & 3) * 2;
            float b0 = 0.0f, b1 = 0.0f;
            if (bias) { b0 = __ldg(bias + cc); b1 = __ldg(bias + cc + 1); }
            const float* c = &acc[mt * 16 + nt * 4];
            float2 v0 = { c[0] + b0, c[1] + b1 };
            float2 v1 = { c[2] + b0, c[3] + b1 };
            *(float2*)(C + (size_t)r * N + cc)       = v0;
            *(float2*)(C + (size_t)(r + 8) * N + cc) = v1;
        }
    }
}

// ---------------------------------------------------------------------------
// SRU recurrence scan. Writes fp32 H and (optionally) tf32-rounded Hr.
// ---------------------------------------------------------------------------
__device__ __forceinline__ float sigm(float x) { return 1.0f / (1.0f + expf(-x)); }

__global__ void sru_scan(const float* __restrict__ U, int ustride,
                         const float* __restrict__ hwIn,
                         const float* __restrict__ bias,
                         const float* __restrict__ c0,
                         float* __restrict__ H,
                         float* __restrict__ Hr, int n_out) {
    int t = blockIdx.x * blockDim.x + threadIdx.x;
    if (t >= BSZ * n_out) return;
    int b = t / n_out;
    int d = t - b * n_out;

    float c  = c0[t];
    float bf = bias[d];
    float br = bias[n_out + d];

    for (int l = 0; l < LSEQ; l++) {
        size_t rowi = (size_t)(l * BSZ + b);
        const float* row = U + rowi * ustride;
        float xt = row[d];
        float f  = sigm(row[n_out + d] + bf);
        float r  = sigm(row[2 * n_out + d] + br);
        float hw = hwIn ? hwIn[rowi * n_out + d] : row[3 * n_out + d];
        c = f * c + (1.0f - f) * xt;
        float gg = tanhf(c);
        float h = r * gg + (1.0f - r) * hw;
        H[rowi * n_out + d] = h;
        if (Hr) Hr[rowi * n_out + d] = tf32r(h);
    }
}

// ---------------------------------------------------------------------------
// Launch
// ---------------------------------------------------------------------------
extern "C" void kernel_launch(void* const* d_in, const int* in_sizes, int n_in,
                              void* d_out, int out_size) {
    const int*   x        = (const int*)  d_in[0];
    const float* c1       = (const float*)d_in[1];
    const float* c2       = (const float*)d_in[2];
    const float* c3       = (const float*)d_in[3];
    const float* emb      = (const float*)d_in[4];
    const float* out_bias = (const float*)d_in[5];
    const float* W1       = (const float*)d_in[6];
    const float* b1       = (const float*)d_in[7];
    const float* W2       = (const float*)d_in[8];
    const float* b2       = (const float*)d_in[9];
    const float* W3       = (const float*)d_in[10];
    const float* b3       = (const float*)d_in[11];
    float* out = (float*)d_out;

    float *H, *U, *Ar, *Br;
    cudaGetSymbolAddress((void**)&H,  gH);
    cudaGetSymbolAddress((void**)&U,  gU);
    cudaGetSymbolAddress((void**)&Ar, gAr);
    cudaGetSymbolAddress((void**)&Br, gBr);

    cudaFuncSetAttribute(gemm_tf32, cudaFuncAttributeMaxDynamicSharedMemorySize, GEMM_SMEM);

    // 1) Embedding gather (rounded directly into Ar)
    embed_gather<<<MROWS, 128>>>(x, emb, Ar);

    // 2) Layer 1 (k=4): N=4096, K=512
    conv_round_T<<<dim3(4 * DDIM / 32, EDIM / 32), dim3(32, 8)>>>(W1, EDIM, 4 * DDIM, Br);
    gemm_tf32<<<dim3(4 * DDIM / 128, MROWS / 128), 256, GEMM_SMEM>>>(
        Ar, Br, U, nullptr, MROWS, 4 * DDIM, EDIM);
    sru_scan<<<(BSZ * DDIM + 255) / 256, 256>>>(U, 4 * DDIM, nullptr, b1, c1, H, Ar, DDIM);

    // 3) Middle layers (k=3): N=3072, K=1024
    for (int i = 0; i < MIDN; i++) {
        const float* Wi = W2 + (size_t)i * DDIM * 3 * DDIM;
        const float* bi = b2 + (size_t)i * 2 * DDIM;
        const float* ci = c2 + (size_t)i * BSZ * DDIM;
        conv_round_T<<<dim3(3 * DDIM / 32, DDIM / 32), dim3(32, 8)>>>(Wi, DDIM, 3 * DDIM, Br);
        gemm_tf32<<<dim3(3 * DDIM / 128, MROWS / 128), 256, GEMM_SMEM>>>(
            Ar, Br, U, nullptr, MROWS, 3 * DDIM, DDIM);
        sru_scan<<<(BSZ * DDIM + 255) / 256, 256>>>(U, 3 * DDIM, H, bi, ci, H, Ar, DDIM);
    }

    // 4) Final layer (k=4): N=2048, K=1024
    conv_round_T<<<dim3(4 * EDIM / 32, DDIM / 32), dim3(32, 8)>>>(W3, DDIM, 4 * EDIM, Br);
    gemm_tf32<<<dim3(4 * EDIM / 128, MROWS / 128), 256, GEMM_SMEM>>>(
        Ar, Br, U, nullptr, MROWS, 4 * EDIM, DDIM);
    sru_scan<<<(BSZ * EDIM + 255) / 256, 256>>>(U, 4 * EDIM, nullptr, b3, c3, H, Ar, EDIM);

    // 5) Logits: out = HF @ emb^T + out_bias (N=32000, K=512); emb already [N,K]
    conv_round<<<(VDIM * EDIM / 4 + 255) / 256, 256>>>(emb, Br, VDIM * EDIM / 4);
    gemm_tf32<<<dim3(VDIM / 128, MROWS / 128), 256, GEMM_SMEM>>>(
        Ar, Br, out, out_bias, MROWS, VDIM, EDIM);
}